// round 6
// baseline (speedup 1.0000x reference)
#include <cuda_runtime.h>

// GlitchSampler: masked scatter of random glitch windows into X, plus y labels.
//
// R6: thin-thread design — one float4 load + one float4 store per thread.
//   - 4096 blocks x 256 threads; block = 1/4 of one (b,c) row.
//     256 threads x 4 floats = 1024 floats = CHUNK_F  (fixes R5's 4x coverage bug).
//   - MLP_p1 per thread = 1 vector (or 4 scalar on the unaligned masked path):
//     shallow L1tex queue -> avoids the cross-CTA queue-contention spread that
//     the fat-MLP R2 kernel (16 front LDGs/thread) hits at oe=8.
//
// Shapes:
//   X [512,2,4096] f32, y [512] f32, glitch_{h,l} [2048,16384] f32,
//   masks/idx/starts [2,512] int32.
// Output: concat(Xo.flatten(), yo.flatten()) = 4,194,304 + 512 f32.

#define Bn 512
#define Cn 2
#define Kn 4096
#define Tn 16384
#define MIN_START 3584
#define CHUNKS 4                 // blocks per row
#define CHUNK_F (Kn / CHUNKS)    // 1024 floats per block
#define TPB 256                  // 256 threads x 4 floats = 1024  ✓

__global__ void __launch_bounds__(TPB)
glitch_sampler_kernel(const float* __restrict__ X,
                      const float* __restrict__ y,
                      const float* __restrict__ gh,
                      const float* __restrict__ gl,
                      const int*   __restrict__ masks,
                      const int*   __restrict__ idx,
                      const int*   __restrict__ starts,
                      float* __restrict__ out)
{
    const int blk = blockIdx.x;
    if (blk < Bn * Cn * CHUNKS) {
        const int row   = blk >> 2;          // 0..1023  (= b*2 + c, X layout [B,C,K])
        const int chunk = blk & 3;
        const int b  = row >> 1;
        const int c  = row & 1;
        const int cb = c * Bn + b;           // metadata layout [C, B]

        const int m = masks[cb];             // uniform per block: L1 broadcast
        const int foff = chunk * CHUNK_F + threadIdx.x * 4;   // float offset in row
        float4* __restrict__ dst4 = (float4*)(out + (long)row * Kn + foff);

        float4 v;
        if (!m) {
            // aligned copy from X
            v = *(const float4*)(X + (long)row * Kn + foff);
        } else {
            // unaligned (4B) gather from a random glitch row: 4 scalar loads
            const float* __restrict__ g = (c == 0) ? gh : gl;
            const float* __restrict__ src =
                g + (long)idx[cb] * Tn + (starts[cb] + MIN_START) + foff;
            v.x = src[0];
            v.y = src[1];
            v.z = src[2];
            v.w = src[3];
        }
        *dst4 = v;
    } else {
        // tail block: y output (512 elements)
        #pragma unroll
        for (int i = 0; i < Bn / TPB; ++i) {
            const int b = i * TPB + threadIdx.x;
            float v = y[b];
            if (masks[0 * Bn + b] != 0) v -= 2.0f;
            if (masks[1 * Bn + b] != 0) v -= 4.0f;
            out[(long)Bn * Cn * Kn + b] = v;
        }
    }
}

extern "C" void kernel_launch(void* const* d_in, const int* in_sizes, int n_in,
                              void* d_out, int out_size)
{
    const float* X      = (const float*)d_in[0];
    const float* y      = (const float*)d_in[1];
    const float* gh     = (const float*)d_in[2];
    const float* gl     = (const float*)d_in[3];
    const int*   masks  = (const int*)  d_in[4];
    const int*   idx    = (const int*)  d_in[5];
    const int*   starts = (const int*)  d_in[6];
    float* out = (float*)d_out;

    glitch_sampler_kernel<<<Bn * Cn * CHUNKS + 1, TPB>>>(
        X, y, gh, gl, masks, idx, starts, out);
}

// round 8
// speedup vs baseline: 1.1099x; 1.1099x over previous
#include <cuda_runtime.h>

// GlitchSampler: masked scatter of random glitch windows into X, plus y labels.
//
// R8 = R7 resubmit (broker failed twice; no kernel evidence against).
// Exact one-wave design:
//   - grid 1184 x 256 = 303,104 threads = 148 SMs x 2048 = ONE full wave:
//     no wave transitions (R6 lost ~3 waves x ~2.4K cyc of transition cost).
//   - each thread: 3-4 independent float4 chunks, loads front-batched then
//     stores (MLP_p1 ~ 4: below the L1tex-contention regime of R2's
//     16-deep front batch, above R6's latency-exposed MLP=1).
//   - chunk stride 303,104 float4 = 296 rows exactly -> constant within-row
//     offset per thread across its chunks.
//   - masked gather alignment tiers (16B / 8B / 4B base, uniform per row).
//   - y folded into threads 0..511 of the same grid (no tail block).
//
// Shapes: X [512,2,4096] f32, y [512] f32, glitch_{h,l} [2048,16384] f32,
//         masks/idx/starts [2,512] int32.
// Output: concat(Xo.flatten(), yo.flatten()) = 4,194,304 + 512 f32.

#define Bn 512
#define Cn 2
#define Kn 4096
#define Tn 16384
#define MIN_START 3584
#define TPB 256
#define GRID 1184
#define NTHREADS (GRID * TPB)                 // 303,104
#define TOTAL_CHUNKS (Bn * Cn * Kn / 4)       // 1,048,576 float4s

__device__ __forceinline__ float4 load_chunk(const float* __restrict__ X,
                                             const float* __restrict__ gh,
                                             const float* __restrict__ gl,
                                             const int*   __restrict__ masks,
                                             const int*   __restrict__ idx,
                                             const int*   __restrict__ starts,
                                             int chunk)
{
    const int row  = chunk >> 10;             // 1024 float4 per row (= b*2 + c)
    const int foff = (chunk & 1023) * 4;      // float offset within row
    const int b  = row >> 1;
    const int c  = row & 1;
    const int cb = c * Bn + b;                // metadata layout [C, B]

    if (!masks[cb]) {
        return *(const float4*)(X + (long)row * Kn + foff);
    }
    const float* __restrict__ g = (c == 0) ? gh : gl;
    const float* __restrict__ src =
        g + (long)idx[cb] * Tn + (starts[cb] + MIN_START) + foff;
    const unsigned a = (unsigned)(size_t)src;
    if ((a & 15u) == 0u) {                    // 16B-aligned window (1/4 of rows)
        return *(const float4*)src;
    } else if ((a & 7u) == 0u) {              // 8B-aligned (1/4 of rows)
        const float2 lo = *(const float2*)src;
        const float2 hi = *(const float2*)(src + 2);
        return make_float4(lo.x, lo.y, hi.x, hi.y);
    } else {                                  // 4B only: scalar x4
        return make_float4(src[0], src[1], src[2], src[3]);
    }
}

__global__ void __launch_bounds__(TPB)
glitch_sampler_kernel(const float* __restrict__ X,
                      const float* __restrict__ y,
                      const float* __restrict__ gh,
                      const float* __restrict__ gl,
                      const int*   __restrict__ masks,
                      const int*   __restrict__ idx,
                      const int*   __restrict__ starts,
                      float* __restrict__ out)
{
    const int tid = blockIdx.x * TPB + threadIdx.x;
    float4* __restrict__ out4 = (float4*)out;

    // chunks tid + i*NTHREADS: i=0,1,2 always in range
    // (max = 303,103 + 2*303,104 = 909,311 < 1,048,576); i=3 conditional.
    float4 v0 = load_chunk(X, gh, gl, masks, idx, starts, tid);
    float4 v1 = load_chunk(X, gh, gl, masks, idx, starts, tid + NTHREADS);
    float4 v2 = load_chunk(X, gh, gl, masks, idx, starts, tid + 2 * NTHREADS);
    const int c3 = tid + 3 * NTHREADS;
    float4 v3;
    const bool has3 = (c3 < TOTAL_CHUNKS);
    if (has3) v3 = load_chunk(X, gh, gl, masks, idx, starts, c3);

    out4[tid]                = v0;
    out4[tid + NTHREADS]     = v1;
    out4[tid + 2 * NTHREADS] = v2;
    if (has3) out4[c3]       = v3;

    // y output: first 512 threads of the grid
    if (tid < Bn) {
        float vy = y[tid];
        if (masks[tid]      != 0) vy -= 2.0f;   // c = 0
        if (masks[Bn + tid] != 0) vy -= 4.0f;   // c = 1
        out[(long)Bn * Cn * Kn + tid] = vy;
    }
}

extern "C" void kernel_launch(void* const* d_in, const int* in_sizes, int n_in,
                              void* d_out, int out_size)
{
    const float* X      = (const float*)d_in[0];
    const float* y      = (const float*)d_in[1];
    const float* gh     = (const float*)d_in[2];
    const float* gl     = (const float*)d_in[3];
    const int*   masks  = (const int*)  d_in[4];
    const int*   idx    = (const int*)  d_in[5];
    const int*   starts = (const int*)  d_in[6];
    float* out = (float*)d_out;

    glitch_sampler_kernel<<<GRID, TPB>>>(X, y, gh, gl, masks, idx, starts, out);
}

// round 9
// speedup vs baseline: 1.1423x; 1.0292x over previous
#include <cuda_runtime.h>

// GlitchSampler: masked scatter of random glitch windows into X, plus y labels.
//
// R9 = R2 shape (1024 row-blocks x 256 + y tail, best measured: 8.8us) with the
// masked gather rewritten for minimal L1tex wavefronts:
//   - old masked path: per-thread 4 consecutive scalars at 16B lane stride
//     -> each scalar LDG warp-op spans 512B = ~5 lines = ~5 wavefronts.
//   - new masked path: INTERLEAVED coalesced scalars — thread t handles floats
//     {t + 256j}; consecutive lanes hit consecutive addresses -> 1-2 wf/op.
//     Loads front-batched (16 in flight), scalar stores equally coalesced.
//   - masked rows whose window base is 16B-aligned (~1/4) use the pure
//     float4 path instead.
//   - unmasked rows: aligned float4 copy from X (unchanged).
//
// Shapes: X [512,2,4096] f32, y [512] f32, glitch_{h,l} [2048,16384] f32,
//         masks/idx/starts [2,512] int32.
// Output: concat(Xo.flatten(), yo.flatten()) = 4,194,304 + 512 f32.

#define Bn 512
#define Cn 2
#define Kn 4096
#define Tn 16384
#define MIN_START 3584
#define TPB 256

__global__ void __launch_bounds__(TPB)
glitch_sampler_kernel(const float* __restrict__ X,
                      const float* __restrict__ y,
                      const float* __restrict__ gh,
                      const float* __restrict__ gl,
                      const int*   __restrict__ masks,
                      const int*   __restrict__ idx,
                      const int*   __restrict__ starts,
                      float* __restrict__ out)
{
    const int row = blockIdx.x;                 // 0..1023 rows; block 1024 = y tail
    const int tid = threadIdx.x;

    if (row < Bn * Cn) {
        const int b  = row >> 1;                // X layout [B,C,K]: row = b*2 + c
        const int c  = row & 1;
        const int cb = c * Bn + b;              // metadata layout [C,B]
        const int m  = masks[cb];

        float* __restrict__ dstf = out + (long)row * Kn;

        const float* srcf;                      // vector-path source (16B aligned)
        bool vector_path;
        const float* src_scalar = nullptr;      // scalar-path source

        if (!m) {
            srcf = X + (long)row * Kn;
            vector_path = true;
        } else {
            const float* __restrict__ g = (c == 0) ? gh : gl;
            const float* s = g + (long)idx[cb] * Tn + (starts[cb] + MIN_START);
            if (((size_t)s & 15u) == 0u) {      // window base 16B aligned
                srcf = s;
                vector_path = true;
            } else {
                src_scalar = s;
                vector_path = false;
            }
        }

        if (vector_path) {
            // aligned float4 copy: 4 front-batched loads, 4 stores
            const float4* __restrict__ s4 = (const float4*)srcf + tid;
            float4*       __restrict__ d4 = (float4*)dstf + tid;
            float4 v0 = s4[0];
            float4 v1 = s4[256];
            float4 v2 = s4[512];
            float4 v3 = s4[768];
            d4[0]   = v0;
            d4[256] = v1;
            d4[512] = v2;
            d4[768] = v3;
        } else {
            // interleaved coalesced scalars: thread t owns floats {t + 256j}.
            // 16 independent loads front-batched, then 16 coalesced stores.
            float f[16];
            #pragma unroll
            for (int j = 0; j < 16; ++j)
                f[j] = src_scalar[tid + 256 * j];
            #pragma unroll
            for (int j = 0; j < 16; ++j)
                dstf[tid + 256 * j] = f[j];
        }
    } else {
        // tail block: y output (512 elements, 256 threads x 2)
        #pragma unroll
        for (int i = 0; i < Bn / TPB; ++i) {
            const int b = i * TPB + tid;
            float v = y[b];
            if (masks[0 * Bn + b] != 0) v -= 2.0f;
            if (masks[1 * Bn + b] != 0) v -= 4.0f;
            out[(long)Bn * Cn * Kn + b] = v;
        }
    }
}

extern "C" void kernel_launch(void* const* d_in, const int* in_sizes, int n_in,
                              void* d_out, int out_size)
{
    const float* X      = (const float*)d_in[0];
    const float* y      = (const float*)d_in[1];
    const float* gh     = (const float*)d_in[2];
    const float* gl     = (const float*)d_in[3];
    const int*   masks  = (const int*)  d_in[4];
    const int*   idx    = (const int*)  d_in[5];
    const int*   starts = (const int*)  d_in[6];
    float* out = (float*)d_out;

    glitch_sampler_kernel<<<Bn * Cn + 1, TPB>>>(X, y, gh, gl, masks, idx, starts, out);
}

// round 11
// speedup vs baseline: 1.2275x; 1.0745x over previous
#include <cuda_runtime.h>

// GlitchSampler: masked scatter of random glitch windows into X, plus y labels.
//
// R11 = R10 resubmit (broker failed twice; no kernel evidence against).
// R9 shape (1024 row-blocks x 256 + y tail; best: 8.77us) plus:
//   1) L2::256B prefetch hints on ALL bulk reads — every block reads a
//      contiguous 16KB span, so each demand load also drags the adjacent
//      128B line into L2: double fetch granularity per round trip.
//      (Prefetch span stays in-bounds: masked window end <= row offset
//      12,799 of 16,384; hints are non-faulting regardless.)
//   2) metadata (masks/idx/starts) loaded unconditionally up front and both
//      candidate base addresses computed BEFORE the branch: masked-path
//      dependent chain drops from 3 memory hops to 2.
//
// Shapes: X [512,2,4096] f32, y [512] f32, glitch_{h,l} [2048,16384] f32,
//         masks/idx/starts [2,512] int32.
// Output: concat(Xo.flatten(), yo.flatten()) = 4,194,304 + 512 f32.

#define Bn 512
#define Cn 2
#define Kn 4096
#define Tn 16384
#define MIN_START 3584
#define TPB 256

__device__ __forceinline__ float4 ldg_pf4(const float4* p)
{
    float4 v;
    asm volatile("ld.global.nc.L2::256B.v4.f32 {%0,%1,%2,%3}, [%4];"
                 : "=f"(v.x), "=f"(v.y), "=f"(v.z), "=f"(v.w)
                 : "l"(p));
    return v;
}

__device__ __forceinline__ float ldg_pf1(const float* p)
{
    float v;
    asm volatile("ld.global.nc.L2::256B.f32 %0, [%1];"
                 : "=f"(v)
                 : "l"(p));
    return v;
}

__global__ void __launch_bounds__(TPB)
glitch_sampler_kernel(const float* __restrict__ X,
                      const float* __restrict__ y,
                      const float* __restrict__ gh,
                      const float* __restrict__ gl,
                      const int*   __restrict__ masks,
                      const int*   __restrict__ idx,
                      const int*   __restrict__ starts,
                      float* __restrict__ out)
{
    const int row = blockIdx.x;                 // 0..1023 rows; block 1024 = y tail
    const int tid = threadIdx.x;

    if (row < Bn * Cn) {
        const int b  = row >> 1;                // X layout [B,C,K]: row = b*2 + c
        const int c  = row & 1;
        const int cb = c * Bn + b;              // metadata layout [C,B]

        // front-load ALL metadata (no branch-dependent loads)
        const int m  = masks[cb];
        const int gi = idx[cb];
        const int gs = starts[cb];

        // both candidate sources computed before the branch
        const float* __restrict__ g   = (c == 0) ? gh : gl;
        const float* __restrict__ gsv = g + (long)gi * Tn + (gs + MIN_START);
        const float* __restrict__ xs  = X + (long)row * Kn;

        float* __restrict__ dstf = out + (long)row * Kn;

        const float* srcf = m ? gsv : xs;
        const bool aligned16 = (((size_t)srcf & 15u) == 0u);  // X path always true

        if (aligned16) {
            // aligned float4 copy: 4 front-batched prefetching loads, 4 stores
            const float4* __restrict__ s4 = (const float4*)srcf + tid;
            float4*       __restrict__ d4 = (float4*)dstf + tid;
            float4 v0 = ldg_pf4(s4 +   0);
            float4 v1 = ldg_pf4(s4 + 256);
            float4 v2 = ldg_pf4(s4 + 512);
            float4 v3 = ldg_pf4(s4 + 768);
            d4[0]   = v0;
            d4[256] = v1;
            d4[512] = v2;
            d4[768] = v3;
        } else {
            // interleaved coalesced scalars: thread t owns floats {t + 256j}.
            // 16 independent prefetching loads, then 16 coalesced stores.
            float f[16];
            #pragma unroll
            for (int j = 0; j < 16; ++j)
                f[j] = ldg_pf1(srcf + tid + 256 * j);
            #pragma unroll
            for (int j = 0; j < 16; ++j)
                dstf[tid + 256 * j] = f[j];
        }
    } else {
        // tail block: y output (512 elements, 256 threads x 2)
        #pragma unroll
        for (int i = 0; i < Bn / TPB; ++i) {
            const int b = i * TPB + tid;
            float v = y[b];
            if (masks[0 * Bn + b] != 0) v -= 2.0f;
            if (masks[1 * Bn + b] != 0) v -= 4.0f;
            out[(long)Bn * Cn * Kn + b] = v;
        }
    }
}

extern "C" void kernel_launch(void* const* d_in, const int* in_sizes, int n_in,
                              void* d_out, int out_size)
{
    const float* X      = (const float*)d_in[0];
    const float* y      = (const float*)d_in[1];
    const float* gh     = (const float*)d_in[2];
    const float* gl     = (const float*)d_in[3];
    const int*   masks  = (const int*)  d_in[4];
    const int*   idx    = (const int*)  d_in[5];
    const int*   starts = (const int*)  d_in[6];
    float* out = (float*)d_out;

    glitch_sampler_kernel<<<Bn * Cn + 1, TPB>>>(X, y, gh, gl, masks, idx, starts, out);
}